// round 2
// baseline (speedup 1.0000x reference)
#include <cuda_runtime.h>
#include <cstdint>

#define B_ 4
#define L_ 512
#define D_ 256
#define U_ 64
#define TI 8
#define TJ 32
#define NTROW (L_/TI)   // 64 row tiles per batch

// scratch for projections (allowed: __device__ globals, no allocation)
__device__ float g_q[B_*L_*U_];
__device__ float g_k[B_*L_*U_];

__device__ __forceinline__ float tanh_ap(float x){ float y; asm("tanh.approx.f32 %0, %1;" : "=f"(y) : "f"(x)); return y; }
__device__ __forceinline__ float ex2_ap(float x){ float y; asm("ex2.approx.f32 %0, %1;" : "=f"(y) : "f"(x)); return y; }
__device__ __forceinline__ unsigned long long dup2(float x){
    unsigned long long r; asm("mov.b64 %0, {%1, %1};" : "=l"(r) : "f"(x)); return r;
}
__device__ __forceinline__ void fma2(unsigned long long &a, unsigned long long x, unsigned long long y){
    asm("fma.rn.f32x2 %0, %1, %2, %0;" : "+l"(a) : "l"(x), "l"(y));
}
__device__ __forceinline__ void mul2(unsigned long long &a, unsigned long long x){
    asm("mul.rn.f32x2 %0, %0, %1;" : "+l"(a) : "l"(x));
}
__device__ __forceinline__ float2 unpack2(unsigned long long v){
    float lo, hi; asm("mov.b64 {%0, %1}, %2;" : "=f"(lo), "=f"(hi) : "l"(v)); return make_float2(lo, hi);
}

// ---------------------------------------------------------------------------
// Phase 1: q = X@Wt ; k = X@Wx + bh   (packed f32x2 over u-pairs)
// 256 blocks x 128 threads. Blocks [0,128): q, [128,256): k.
// Each block: 16 rows (2 rows per thread). W staged in smem in two 128-row halves.
// ---------------------------------------------------------------------------
__global__ void __launch_bounds__(128) proj_kernel(
    const float* __restrict__ X, const float* __restrict__ Wt,
    const float* __restrict__ Wx, const float* __restrict__ bh)
{
    __shared__ __align__(16) float W_s[128*U_];   // 32KB (half of W)
    __shared__ __align__(16) float x_s[16*D_];    // 16KB

    const int bid = blockIdx.x;
    const bool is_k = bid >= (B_*L_/16);
    const int rb = is_k ? bid - (B_*L_/16) : bid;
    const float* __restrict__ W = is_k ? Wx : Wt;
    const int t = threadIdx.x;
    const int row0 = rb * 16;

    for (int i = t; i < 16*D_; i += 128)
        x_s[i] = X[row0*D_ + i];

    const int quad = t & 15;        // u = quad*4
    const int r    = t >> 4;        // rows r and r+8
    const float* xr0 = x_s + r*D_;
    const float* xr1 = x_s + (r+8)*D_;

    unsigned long long a01_0 = 0ull, a23_0 = 0ull;
    unsigned long long a01_1 = 0ull, a23_1 = 0ull;

    #pragma unroll
    for (int half = 0; half < 2; ++half) {
        __syncthreads();
        for (int i = t; i < 128*U_; i += 128) W_s[i] = W[half*128*U_ + i];
        __syncthreads();
        const float* x0 = xr0 + half*128;
        const float* x1 = xr1 + half*128;
        #pragma unroll 4
        for (int d = 0; d < 128; ++d) {
            ulonglong2 w2 = *reinterpret_cast<const ulonglong2*>(W_s + d*U_ + quad*4);
            unsigned long long xx0 = dup2(x0[d]);
            unsigned long long xx1 = dup2(x1[d]);
            fma2(a01_0, xx0, w2.x);
            fma2(a23_0, xx0, w2.y);
            fma2(a01_1, xx1, w2.x);
            fma2(a23_1, xx1, w2.y);
        }
    }

    float bx = 0.f, by = 0.f, bz = 0.f, bw = 0.f;
    if (is_k) { bx = bh[quad*4+0]; by = bh[quad*4+1]; bz = bh[quad*4+2]; bw = bh[quad*4+3]; }

    float* base = (is_k ? g_k : g_q);
    {
        float2 v01 = unpack2(a01_0), v23 = unpack2(a23_0);
        float4 o; o.x = v01.x+bx; o.y = v01.y+by; o.z = v23.x+bz; o.w = v23.y+bw;
        *reinterpret_cast<float4*>(base + (row0 + r)*U_ + quad*4) = o;
    }
    {
        float2 v01 = unpack2(a01_1), v23 = unpack2(a23_1);
        float4 o; o.x = v01.x+bx; o.y = v01.y+by; o.z = v23.x+bz; o.w = v23.y+bw;
        *reinterpret_cast<float4*>(base + (row0 + r + 8)*U_ + quad*4) = o;
    }
}

// ---------------------------------------------------------------------------
// Phase 2: flash-style causal additive attention.
// 256 CTAs x 256 threads. ONE row-tile per CTA, LPT-ordered:
//   rank = bid>>2 (0..63), b = bid&3, it = 63 - rank
// so the biggest tiles (most j-work) occupy the first scheduling wave and the
// small tiles backfill as SMs drain. Up to 4 CTAs co-resident per SM
// (smem 45KB, 64 regs) -> cross-CTA latency hiding.
// Score: warp w = row i0+w, lane = j. exp domain = log2 (Wa pre-scaled).
// PV: thread t -> d-pair (t&127), row-half (t>>7); packed fma.rn.f32x2.
// ---------------------------------------------------------------------------
__global__ void __launch_bounds__(256) attn_kernel(
    const float* __restrict__ X, const float* __restrict__ Wa,
    float* __restrict__ out)
{
    __shared__ __align__(16) float4 k_q[16*TJ];     // [uq][j]   8KB
    __shared__ __align__(16) float  Xs[TJ*D_];      // [j][d]    32KB
    __shared__ __align__(16) float4 q_q[16*TI];     // [uq][i]   2KB
    __shared__ __align__(16) float4 wa4[16];        // 256B (pre-scaled by log2e)
    __shared__ __align__(16) float2 p2[TI][TJ];     // dup pairs 2KB
    __shared__ __align__(16) float2 alpha2[TI];
    __shared__ float sinv[TI];

    const int t = threadIdx.x;
    const int w = t >> 5, lane = t & 31;
    const int b  = blockIdx.x & 3;
    const int it = NTROW - 1 - (blockIdx.x >> 2);   // LPT: big tiles first

    const float* __restrict__ Xb = X   + b*L_*D_;
    const float* __restrict__ kb = g_k + b*L_*U_;
    const float* __restrict__ qb = g_q + b*L_*U_;

    if (t < U_) reinterpret_cast<float*>(wa4)[t] = Wa[t] * 1.4426950408889634f;

    const int dp  = t & 127;   // d pair index (d = 2dp, 2dp+1)
    const int ih  = t >> 7;    // row half: rows ih*4 .. ih*4+3
    const int ib0 = ih * 4;

    const int i0  = it * TI;
    const int ntj = (i0 + TI - 1)/TJ + 1;

    if (t < 16*TI) {
        int i = t >> 4, uq = t & 15;
        q_q[uq*TI + i] = *reinterpret_cast<const float4*>(qb + (i0+i)*U_ + uq*4);
    }

    float m_run = -1e30f, s_run = 0.f;
    unsigned long long acc[4] = {0ull, 0ull, 0ull, 0ull};
    const int gi = i0 + w;

    for (int jt = 0; jt < ntj; ++jt) {
        const int j0 = jt * TJ;
        __syncthreads();   // prev v-update done (and q_q/wa4 ready on first iter)

        // ---- load k tile [uq][j] and X tile [j][d] ----
        #pragma unroll
        for (int rep = 0; rep < 2; ++rep) {
            int idx = t + rep*256;
            int uq = idx & 15, j = idx >> 4;
            k_q[uq*TJ + j] = *reinterpret_cast<const float4*>(kb + (j0+j)*U_ + uq*4);
        }
        #pragma unroll
        for (int rr = 0; rr < TJ; ++rr)
            Xs[rr*D_ + t] = Xb[(j0+rr)*D_ + t];
        __syncthreads();

        // ---- score: e[gi][j0+lane] in log2 domain ----
        float e0 = 0.f, e1 = 0.f;
        #pragma unroll
        for (int uq = 0; uq < 16; ++uq) {
            float4 kv = k_q[uq*TJ + lane];   // conflict-free
            float4 qv = q_q[uq*TI + w];      // broadcast
            float4 wa = wa4[uq];             // broadcast
            e0 += wa.x * tanh_ap(qv.x + kv.x);
            e1 += wa.y * tanh_ap(qv.y + kv.y);
            e0 += wa.z * tanh_ap(qv.z + kv.z);
            e1 += wa.w * tanh_ap(qv.w + kv.w);
        }
        float e = e0 + e1;
        const int gj = j0 + lane;
        if (gj > gi) e = -1e30f;   // causal: exp2 underflows to exact 0 (== ref's -10000 path)

        // ---- online softmax (warp = one row) ----
        float mt = e;
        #pragma unroll
        for (int off = 16; off; off >>= 1)
            mt = fmaxf(mt, __shfl_xor_sync(0xffffffffu, mt, off));
        float m_new = fmaxf(m_run, mt);
        float p = ex2_ap(e - m_new);
        float st = p;
        #pragma unroll
        for (int off = 16; off; off >>= 1)
            st += __shfl_xor_sync(0xffffffffu, st, off);
        float alpha = ex2_ap(m_run - m_new);
        s_run = s_run * alpha + st;
        m_run = m_new;
        p2[w][lane] = make_float2(p, p);            // pre-duplicated for f32x2
        if (lane == 0) alpha2[w] = make_float2(alpha, alpha);
        __syncthreads();

        // ---- PV update (packed f32x2 over d-pairs) ----
        #pragma unroll
        for (int i = 0; i < 4; ++i)
            mul2(acc[i], *reinterpret_cast<unsigned long long*>(&alpha2[ib0+i]));
        const unsigned long long* xcol =
            reinterpret_cast<const unsigned long long*>(Xs) + dp;   // stride 128/row
        #pragma unroll
        for (int j = 0; j < TJ; ++j) {
            unsigned long long xv = xcol[j*(D_/2)];
            #pragma unroll
            for (int i = 0; i < 4; ++i)
                fma2(acc[i], xv, *reinterpret_cast<const unsigned long long*>(&p2[ib0+i][j]));
        }
    }

    // ---- finalize ----
    if (lane == 0) sinv[w] = 1.0f / s_run;
    __syncthreads();
    #pragma unroll
    for (int i = 0; i < 4; ++i) {
        float2 v = unpack2(acc[i]);
        float is = sinv[ib0 + i];
        float2 o = make_float2(v.x * is, v.y * is);
        *reinterpret_cast<float2*>(out + (b*L_ + i0 + ib0 + i)*D_ + dp*2) = o;
    }
}

// ---------------------------------------------------------------------------
extern "C" void kernel_launch(void* const* d_in, const int* in_sizes, int n_in,
                              void* d_out, int out_size)
{
    const float* X  = (const float*)d_in[0];
    const float* Wt = (const float*)d_in[1];
    const float* Wx = (const float*)d_in[2];
    const float* bh = (const float*)d_in[3];
    const float* Wa = (const float*)d_in[4];
    // d_in[5] = ba : constant shift inside softmax -> mathematically a no-op

    proj_kernel<<<2*(B_*L_/16), 128>>>(X, Wt, Wx, bh);
    attn_kernel<<<B_*NTROW, 256>>>(X, Wa, (float*)d_out);
}

// round 3
// speedup vs baseline: 1.1165x; 1.1165x over previous
#include <cuda_runtime.h>
#include <cstdint>

#define B_ 4
#define L_ 512
#define D_ 256
#define U_ 64
#define TI 8
#define TJ 32
#define NTROW (L_/TI)   // 64 row tiles per batch

// scratch for projections (allowed: __device__ globals, no allocation)
__device__ float g_q[B_*L_*U_];
__device__ float g_k[B_*L_*U_];

__device__ __forceinline__ float tanh_ap(float x){ float y; asm("tanh.approx.f32 %0, %1;" : "=f"(y) : "f"(x)); return y; }
__device__ __forceinline__ float ex2_ap(float x){ float y; asm("ex2.approx.f32 %0, %1;" : "=f"(y) : "f"(x)); return y; }
__device__ __forceinline__ unsigned long long dup2(float x){
    unsigned long long r; asm("mov.b64 %0, {%1, %1};" : "=l"(r) : "f"(x)); return r;
}
__device__ __forceinline__ unsigned long long pack2(float2 v){
    unsigned long long r; asm("mov.b64 %0, {%1, %2};" : "=l"(r) : "f"(v.x), "f"(v.y)); return r;
}
__device__ __forceinline__ void fma2(unsigned long long &a, unsigned long long x, unsigned long long y){
    asm("fma.rn.f32x2 %0, %1, %2, %0;" : "+l"(a) : "l"(x), "l"(y));
}
__device__ __forceinline__ void mul2(unsigned long long &a, unsigned long long x){
    asm("mul.rn.f32x2 %0, %0, %1;" : "+l"(a) : "l"(x));
}
__device__ __forceinline__ float2 unpack2(unsigned long long v){
    float lo, hi; asm("mov.b64 {%0, %1}, %2;" : "=f"(lo), "=f"(hi) : "l"(v)); return make_float2(lo, hi);
}

// ---------------------------------------------------------------------------
// Phase 1: q = X@Wt ; k = X@Wx + bh   (packed f32x2 over u-pairs)
// 256 blocks x 128 threads. Blocks [0,128): q, [128,256): k.
// Each block: 16 rows (2 rows per thread). W staged in smem in two 128-row halves.
// ---------------------------------------------------------------------------
__global__ void __launch_bounds__(128) proj_kernel(
    const float* __restrict__ X, const float* __restrict__ Wt,
    const float* __restrict__ Wx, const float* __restrict__ bh)
{
    __shared__ __align__(16) float W_s[128*U_];   // 32KB (half of W)
    __shared__ __align__(16) float x_s[16*D_];    // 16KB

    const int bid = blockIdx.x;
    const bool is_k = bid >= (B_*L_/16);
    const int rb = is_k ? bid - (B_*L_/16) : bid;
    const float* __restrict__ W = is_k ? Wx : Wt;
    const int t = threadIdx.x;
    const int row0 = rb * 16;

    for (int i = t; i < 16*D_; i += 128)
        x_s[i] = X[row0*D_ + i];

    const int quad = t & 15;        // u = quad*4
    const int r    = t >> 4;        // rows r and r+8
    const float* xr0 = x_s + r*D_;
    const float* xr1 = x_s + (r+8)*D_;

    unsigned long long a01_0 = 0ull, a23_0 = 0ull;
    unsigned long long a01_1 = 0ull, a23_1 = 0ull;

    #pragma unroll
    for (int half = 0; half < 2; ++half) {
        __syncthreads();
        for (int i = t; i < 128*U_; i += 128) W_s[i] = W[half*128*U_ + i];
        __syncthreads();
        const float* x0 = xr0 + half*128;
        const float* x1 = xr1 + half*128;
        #pragma unroll 4
        for (int d = 0; d < 128; ++d) {
            ulonglong2 w2 = *reinterpret_cast<const ulonglong2*>(W_s + d*U_ + quad*4);
            unsigned long long xx0 = dup2(x0[d]);
            unsigned long long xx1 = dup2(x1[d]);
            fma2(a01_0, xx0, w2.x);
            fma2(a23_0, xx0, w2.y);
            fma2(a01_1, xx1, w2.x);
            fma2(a23_1, xx1, w2.y);
        }
    }

    float bx = 0.f, by = 0.f, bz = 0.f, bw = 0.f;
    if (is_k) { bx = bh[quad*4+0]; by = bh[quad*4+1]; bz = bh[quad*4+2]; bw = bh[quad*4+3]; }

    float* base = (is_k ? g_k : g_q);
    {
        float2 v01 = unpack2(a01_0), v23 = unpack2(a23_0);
        float4 o; o.x = v01.x+bx; o.y = v01.y+by; o.z = v23.x+bz; o.w = v23.y+bw;
        *reinterpret_cast<float4*>(base + (row0 + r)*U_ + quad*4) = o;
    }
    {
        float2 v01 = unpack2(a01_1), v23 = unpack2(a23_1);
        float4 o; o.x = v01.x+bx; o.y = v01.y+by; o.z = v23.x+bz; o.w = v23.y+bw;
        *reinterpret_cast<float4*>(base + (row0 + r + 8)*U_ + quad*4) = o;
    }
}

// ---------------------------------------------------------------------------
// Phase 2: flash-style causal additive attention. 128 CTAs x 256 threads,
// paired tiles {pr, 63-pr} (uniform ~17 j-tile units per CTA, one wave).
// L1-traffic-minimized vs R1:
//   - X never staged in smem: PV reads X via coalesced LDG.64 (L1-cached),
//     software-pipelined in chunks of 4 j-rows.
//   - p stored non-duplicated; PV loads it as warp-uniform LDS.128 (4 j/load),
//     duplication for f32x2 done in ALU (idle pipe).
//   - k tile double-buffered; next tile's fill issued before PV so its
//     LDG->STS latency hides under PV compute.
// ---------------------------------------------------------------------------
__global__ void __launch_bounds__(256) attn_kernel(
    const float* __restrict__ X, const float* __restrict__ Wa,
    float* __restrict__ out)
{
    __shared__ __align__(16) float4 kbuf[2][16*TJ];   // [buf][uq*TJ+j] 16KB
    __shared__ __align__(16) float4 q_q[16*TI];       // [uq*TI+i]      2KB
    __shared__ __align__(16) float4 wa4[16];          // 256B (pre-scaled by log2e)
    __shared__ __align__(16) float  p4[TI][TJ];       // 1KB (non-dup)
    __shared__ float alpha_s[TI];
    __shared__ float sinv[TI];

    const int t = threadIdx.x;
    const int w = t >> 5, lane = t & 31;
    const int b  = blockIdx.x >> 5;
    const int pr = blockIdx.x & 31;

    const float* __restrict__ Xb = X   + b*L_*D_;
    const float* __restrict__ kb = g_k + b*L_*U_;
    const float* __restrict__ qb = g_q + b*L_*U_;
    const float2* __restrict__ Xb2 = reinterpret_cast<const float2*>(Xb);

    if (t < U_) reinterpret_cast<float*>(wa4)[t] = Wa[t] * 1.4426950408889634f;

    const int dp  = t & 127;   // d pair index (d = 2dp, 2dp+1)
    const int ih  = t >> 7;    // row half
    const int ib0 = ih * 4;    // rows ib0..ib0+3

    for (int pass = 0; pass < 2; ++pass) {
        const int it = pass ? (NTROW - 1 - pr) : pr;
        const int i0 = it * TI;
        const int ntj = (i0 + TI - 1)/TJ + 1;
        const int gi = i0 + w;

        __syncthreads();   // prior pass fully done with smem
        if (t < 16*TI) {
            int i = t >> 4, uq = t & 15;
            q_q[uq*TI + i] = *reinterpret_cast<const float4*>(qb + (i0+i)*U_ + uq*4);
        }
        // fill k buffer 0 (j-tile 0)
        #pragma unroll
        for (int rep = 0; rep < 2; ++rep) {
            int idx = t + rep*256;
            int uq = idx & 15, j = idx >> 4;
            kbuf[0][uq*TJ + j] = *reinterpret_cast<const float4*>(kb + j*U_ + uq*4);
        }
        __syncthreads();

        float m_run = -1e30f, s_run = 0.f;
        unsigned long long acc[4] = {0ull, 0ull, 0ull, 0ull};

        for (int jt = 0; jt < ntj; ++jt) {
            const int j0 = jt * TJ;
            const float4* kc = kbuf[jt & 1];

            // ---- score: e[gi][j0+lane] in log2 domain ----
            float e0 = 0.f, e1 = 0.f;
            #pragma unroll
            for (int uq = 0; uq < 16; ++uq) {
                float4 kv = kc[uq*TJ + lane];    // conflict-free
                float4 qv = q_q[uq*TI + w];      // broadcast
                float4 wa = wa4[uq];             // broadcast
                e0 += wa.x * tanh_ap(qv.x + kv.x);
                e1 += wa.y * tanh_ap(qv.y + kv.y);
                e0 += wa.z * tanh_ap(qv.z + kv.z);
                e1 += wa.w * tanh_ap(qv.w + kv.w);
            }
            float e = e0 + e1;
            const int gj = j0 + lane;
            if (gj > gi) e = -1e30f;   // exp2 underflows to exact 0 (== ref's -10000 path)

            // ---- online softmax (warp = one row) ----
            float mt = e;
            #pragma unroll
            for (int off = 16; off; off >>= 1)
                mt = fmaxf(mt, __shfl_xor_sync(0xffffffffu, mt, off));
            float m_new = fmaxf(m_run, mt);
            float p = ex2_ap(e - m_new);
            float st = p;
            #pragma unroll
            for (int off = 16; off; off >>= 1)
                st += __shfl_xor_sync(0xffffffffu, st, off);
            float alpha = ex2_ap(m_run - m_new);
            s_run = s_run * alpha + st;
            m_run = m_new;
            p4[w][lane] = p;
            if (lane == 0) alpha_s[w] = alpha;
            __syncthreads();

            // ---- prefetch next k tile (latency hides under PV below) ----
            if (jt + 1 < ntj) {
                float4* kn = kbuf[(jt + 1) & 1];
                const int j0n = j0 + TJ;
                #pragma unroll
                for (int rep = 0; rep < 2; ++rep) {
                    int idx = t + rep*256;
                    int uq = idx & 15, j = idx >> 4;
                    kn[uq*TJ + j] = *reinterpret_cast<const float4*>(kb + (j0n+j)*U_ + uq*4);
                }
            }

            // ---- PV update: acc = acc*alpha + sum_j p[i][j] * X[j][d-pair] ----
            {
                unsigned long long av = dup2(alpha_s[ib0]);       // rows share? no:
                // per-row alpha: apply individually
            }
            #pragma unroll
            for (int i = 0; i < 4; ++i)
                mul2(acc[i], dup2(alpha_s[ib0+i]));

            // software-pipelined chunks of 4 j-rows
            float2 xr[4];
            #pragma unroll
            for (int j4 = 0; j4 < 4; ++j4)
                xr[j4] = Xb2[(j0 + j4)*(D_/2) + dp];

            #pragma unroll
            for (int jc = 0; jc < TJ/4; ++jc) {
                float2 xn[4];
                if (jc + 1 < TJ/4) {
                    #pragma unroll
                    for (int j4 = 0; j4 < 4; ++j4)
                        xn[j4] = Xb2[(j0 + (jc+1)*4 + j4)*(D_/2) + dp];
                }
                float4 pv[4];
                #pragma unroll
                for (int i = 0; i < 4; ++i)
                    pv[i] = *reinterpret_cast<const float4*>(&p4[ib0+i][jc*4]);

                #pragma unroll
                for (int j4 = 0; j4 < 4; ++j4) {
                    unsigned long long xx = pack2(xr[j4]);
                    const float* pf0 = reinterpret_cast<const float*>(&pv[0]);
                    const float* pf1 = reinterpret_cast<const float*>(&pv[1]);
                    const float* pf2 = reinterpret_cast<const float*>(&pv[2]);
                    const float* pf3 = reinterpret_cast<const float*>(&pv[3]);
                    fma2(acc[0], xx, dup2(pf0[j4]));
                    fma2(acc[1], xx, dup2(pf1[j4]));
                    fma2(acc[2], xx, dup2(pf2[j4]));
                    fma2(acc[3], xx, dup2(pf3[j4]));
                }
                if (jc + 1 < TJ/4) {
                    #pragma unroll
                    for (int j4 = 0; j4 < 4; ++j4) xr[j4] = xn[j4];
                }
            }
            __syncthreads();   // k fill visible; p consumed before next overwrite
        }

        // ---- finalize ----
        if (lane == 0) sinv[w] = 1.0f / s_run;
        __syncthreads();
        #pragma unroll
        for (int i = 0; i < 4; ++i) {
            float2 v = unpack2(acc[i]);
            float is = sinv[ib0 + i];
            float2 o = make_float2(v.x * is, v.y * is);
            *reinterpret_cast<float2*>(out + (b*L_ + i0 + ib0 + i)*D_ + dp*2) = o;
        }
    }
}

// ---------------------------------------------------------------------------
extern "C" void kernel_launch(void* const* d_in, const int* in_sizes, int n_in,
                              void* d_out, int out_size)
{
    const float* X  = (const float*)d_in[0];
    const float* Wt = (const float*)d_in[1];
    const float* Wx = (const float*)d_in[2];
    const float* bh = (const float*)d_in[3];
    const float* Wa = (const float*)d_in[4];
    // d_in[5] = ba : constant shift inside softmax -> mathematically a no-op

    proj_kernel<<<2*(B_*L_/16), 128>>>(X, Wt, Wx, bh);
    attn_kernel<<<B_*(NTROW/2), 256>>>(X, Wa, (float*)d_out);
}

// round 4
// speedup vs baseline: 1.2275x; 1.0994x over previous
#include <cuda_runtime.h>
#include <cstdint>

#define B_ 4
#define L_ 512
#define D_ 256
#define U_ 64
#define TI 8
#define TJ 32
#define NTROW (L_/TI)   // 64 row tiles per batch

// scratch for projections (allowed: __device__ globals, no allocation)
__device__ float g_q[B_*L_*U_];
__device__ float g_k[B_*L_*U_];

__device__ __forceinline__ float tanh_ap(float x){ float y; asm("tanh.approx.f32 %0, %1;" : "=f"(y) : "f"(x)); return y; }
__device__ __forceinline__ float ex2_ap(float x){ float y; asm("ex2.approx.f32 %0, %1;" : "=f"(y) : "f"(x)); return y; }
__device__ __forceinline__ unsigned long long dup2(float x){
    unsigned long long r; asm("mov.b64 %0, {%1, %1};" : "=l"(r) : "f"(x)); return r;
}
__device__ __forceinline__ unsigned long long pack2(float2 v){
    unsigned long long r; asm("mov.b64 %0, {%1, %2};" : "=l"(r) : "f"(v.x), "f"(v.y)); return r;
}
__device__ __forceinline__ void fma2(unsigned long long &a, unsigned long long x, unsigned long long y){
    asm("fma.rn.f32x2 %0, %1, %2, %0;" : "+l"(a) : "l"(x), "l"(y));
}
__device__ __forceinline__ float2 unpack2(unsigned long long v){
    float lo, hi; asm("mov.b64 {%0, %1}, %2;" : "=f"(lo), "=f"(hi) : "l"(v)); return make_float2(lo, hi);
}

// ---------------------------------------------------------------------------
// Phase 1: q = X@Wt ; k = X@Wx + bh   (packed f32x2 over u-pairs)
// 256 blocks x 128 threads. Blocks [0,128): q, [128,256): k.
// Each block: 16 rows (2 rows per thread). W staged in smem in two 128-row halves.
// ---------------------------------------------------------------------------
__global__ void __launch_bounds__(128) proj_kernel(
    const float* __restrict__ X, const float* __restrict__ Wt,
    const float* __restrict__ Wx, const float* __restrict__ bh)
{
    __shared__ __align__(16) float W_s[128*U_];   // 32KB (half of W)
    __shared__ __align__(16) float x_s[16*D_];    // 16KB

    const int bid = blockIdx.x;
    const bool is_k = bid >= (B_*L_/16);
    const int rb = is_k ? bid - (B_*L_/16) : bid;
    const float* __restrict__ W = is_k ? Wx : Wt;
    const int t = threadIdx.x;
    const int row0 = rb * 16;

    for (int i = t; i < 16*D_; i += 128)
        x_s[i] = X[row0*D_ + i];

    const int quad = t & 15;        // u = quad*4
    const int r    = t >> 4;        // rows r and r+8
    const float* xr0 = x_s + r*D_;
    const float* xr1 = x_s + (r+8)*D_;

    unsigned long long a01_0 = 0ull, a23_0 = 0ull;
    unsigned long long a01_1 = 0ull, a23_1 = 0ull;

    #pragma unroll
    for (int half = 0; half < 2; ++half) {
        __syncthreads();
        for (int i = t; i < 128*U_; i += 128) W_s[i] = W[half*128*U_ + i];
        __syncthreads();
        const float* x0 = xr0 + half*128;
        const float* x1 = xr1 + half*128;
        #pragma unroll 4
        for (int d = 0; d < 128; ++d) {
            ulonglong2 w2 = *reinterpret_cast<const ulonglong2*>(W_s + d*U_ + quad*4);
            unsigned long long xx0 = dup2(x0[d]);
            unsigned long long xx1 = dup2(x1[d]);
            fma2(a01_0, xx0, w2.x);
            fma2(a23_0, xx0, w2.y);
            fma2(a01_1, xx1, w2.x);
            fma2(a23_1, xx1, w2.y);
        }
    }

    float bx = 0.f, by = 0.f, bz = 0.f, bw = 0.f;
    if (is_k) { bx = bh[quad*4+0]; by = bh[quad*4+1]; bz = bh[quad*4+2]; bw = bh[quad*4+3]; }

    float* base = (is_k ? g_k : g_q);
    {
        float2 v01 = unpack2(a01_0), v23 = unpack2(a23_0);
        float4 o; o.x = v01.x+bx; o.y = v01.y+by; o.z = v23.x+bz; o.w = v23.y+bw;
        *reinterpret_cast<float4*>(base + (row0 + r)*U_ + quad*4) = o;
    }
    {
        float2 v01 = unpack2(a01_1), v23 = unpack2(a23_1);
        float4 o; o.x = v01.x+bx; o.y = v01.y+by; o.z = v23.x+bz; o.w = v23.y+bw;
        *reinterpret_cast<float4*>(base + (row0 + r + 8)*U_ + quad*4) = o;
    }
}

// ---------------------------------------------------------------------------
// Phase 2: causal additive attention, DE-INTERLEAVED two-pass softmax.
// 128 CTAs x 256 threads, paired tiles {pr, 63-pr} (uniform work, 1 wave).
// Per row-tile:
//   A) score-only sweep over all j-tiles -> es[8][512] smem buffer
//      (warp=row, lane=j; k double-buffered; ONLY per-lane running max;
//       no reductions / softmax / PV inside the loop => MUFU runs hot)
//   B) warp-local max reduce, one ex2 sweep in place (p overwrites e), sum
//   C) one clean PV GEMM loop over the whole j-range: p broadcast from smem,
//      X coalesced LDG (L2-resident), packed f32x2, unroll 8 for MLP.
// ---------------------------------------------------------------------------
__global__ void __launch_bounds__(256, 1) attn_kernel(
    const float* __restrict__ X, const float* __restrict__ Wa,
    float* __restrict__ out)
{
    __shared__ float es[TI*L_];                       // 16KB  scores -> p
    __shared__ __align__(16) float4 kbuf[2][16*TJ];   // 16KB  k double buffer
    __shared__ __align__(16) float4 q_q[16*TI];       // 2KB
    __shared__ __align__(16) float4 wa4[16];          // 256B (pre-scaled log2e)
    __shared__ float sinv[TI];

    const int t = threadIdx.x;
    const int w = t >> 5, lane = t & 31;
    const int b  = blockIdx.x >> 5;
    const int pr = blockIdx.x & 31;

    const float* __restrict__ Xb = X   + b*L_*D_;
    const float* __restrict__ kb = g_k + b*L_*U_;
    const float* __restrict__ qb = g_q + b*L_*U_;
    const float2* __restrict__ Xb2 = reinterpret_cast<const float2*>(Xb);

    if (t < U_) reinterpret_cast<float*>(wa4)[t] = Wa[t] * 1.4426950408889634f;

    const int dp  = t & 127;   // d-pair (d = 2dp, 2dp+1)
    const int ih  = t >> 7;
    const int ib0 = ih * 4;    // PV rows ib0..ib0+3

    for (int pass = 0; pass < 2; ++pass) {
        const int it = pass ? (NTROW - 1 - pr) : pr;
        const int i0 = it * TI;
        const int ntj = (i0 + TI - 1)/TJ + 1;
        const int gi = i0 + w;

        __syncthreads();   // prior pass fully done with smem
        if (t < 16*TI) {
            int i = t >> 4, uq = t & 15;
            q_q[uq*TI + i] = *reinterpret_cast<const float4*>(qb + (i0+i)*U_ + uq*4);
        }
        // fill k buffer 0 (j-tile 0)
        #pragma unroll
        for (int rep = 0; rep < 2; ++rep) {
            int idx = t + rep*256;
            int uq = idx & 15, j = idx >> 4;
            kbuf[0][uq*TJ + j] = *reinterpret_cast<const float4*>(kb + j*U_ + uq*4);
        }

        // ================= Phase A: scores only =================
        float m_lane = -1e30f;
        for (int jt = 0; jt < ntj; ++jt) {
            const int j0 = jt * TJ;
            __syncthreads();   // buf[jt&1] ready; readers of buf[(jt+1)&1] done
            if (jt + 1 < ntj) {
                float4* kn = kbuf[(jt + 1) & 1];
                #pragma unroll
                for (int rep = 0; rep < 2; ++rep) {
                    int idx = t + rep*256;
                    int uq = idx & 15, j = idx >> 4;
                    kn[uq*TJ + j] = *reinterpret_cast<const float4*>(kb + (j0+TJ+j)*U_ + uq*4);
                }
            }
            float e = -1e30f;
            if (j0 <= gi) {                    // warp-uniform branch
                const float4* kc = kbuf[jt & 1];
                float e0 = 0.f, e1 = 0.f;
                #pragma unroll
                for (int uq = 0; uq < 16; ++uq) {
                    float4 kv = kc[uq*TJ + lane];    // conflict-free
                    float4 qv = q_q[uq*TI + w];      // broadcast
                    float4 wa = wa4[uq];             // broadcast
                    e0 += wa.x * tanh_ap(qv.x + kv.x);
                    e1 += wa.y * tanh_ap(qv.y + kv.y);
                    e0 += wa.z * tanh_ap(qv.z + kv.z);
                    e1 += wa.w * tanh_ap(qv.w + kv.w);
                }
                e = e0 + e1;
                if (j0 + lane > gi) e = -1e30f;  // causal: exp2 -> exact 0
            }
            es[w*L_ + j0 + lane] = e;
            m_lane = fmaxf(m_lane, e);
        }

        // ================= Phase B: softmax (warp-local) =================
        #pragma unroll
        for (int off = 16; off; off >>= 1)
            m_lane = fmaxf(m_lane, __shfl_xor_sync(0xffffffffu, m_lane, off));
        const float m = m_lane;
        float s_lane = 0.f;
        const int jend = ntj * TJ;
        for (int jj = lane; jj < jend; jj += 32) {
            float p = ex2_ap(es[w*L_ + jj] - m);
            es[w*L_ + jj] = p;
            s_lane += p;
        }
        #pragma unroll
        for (int off = 16; off; off >>= 1)
            s_lane += __shfl_xor_sync(0xffffffffu, s_lane, off);
        if (lane == 0) sinv[w] = 1.0f / s_lane;
        __syncthreads();   // p + sinv visible to all

        // ================= Phase C: PV GEMM =================
        unsigned long long acc[4] = {0ull, 0ull, 0ull, 0ull};
        for (int jb = 0; jb < jend; jb += 8) {
            float2 xv[8];
            #pragma unroll
            for (int j = 0; j < 8; ++j)
                xv[j] = Xb2[(jb + j)*(D_/2) + dp];          // coalesced, L2-hit
            float4 pA[4], pB[4];
            #pragma unroll
            for (int i = 0; i < 4; ++i) {
                pA[i] = *reinterpret_cast<const float4*>(&es[(ib0+i)*L_ + jb]);      // broadcast
                pB[i] = *reinterpret_cast<const float4*>(&es[(ib0+i)*L_ + jb + 4]);  // broadcast
            }
            #pragma unroll
            for (int j = 0; j < 4; ++j) {
                unsigned long long xx = pack2(xv[j]);
                const float* p0 = reinterpret_cast<const float*>(&pA[0]);
                const float* p1 = reinterpret_cast<const float*>(&pA[1]);
                const float* p2 = reinterpret_cast<const float*>(&pA[2]);
                const float* p3 = reinterpret_cast<const float*>(&pA[3]);
                fma2(acc[0], xx, dup2(p0[j]));
                fma2(acc[1], xx, dup2(p1[j]));
                fma2(acc[2], xx, dup2(p2[j]));
                fma2(acc[3], xx, dup2(p3[j]));
            }
            #pragma unroll
            for (int j = 0; j < 4; ++j) {
                unsigned long long xx = pack2(xv[4 + j]);
                const float* p0 = reinterpret_cast<const float*>(&pB[0]);
                const float* p1 = reinterpret_cast<const float*>(&pB[1]);
                const float* p2 = reinterpret_cast<const float*>(&pB[2]);
                const float* p3 = reinterpret_cast<const float*>(&pB[3]);
                fma2(acc[0], xx, dup2(p0[j]));
                fma2(acc[1], xx, dup2(p1[j]));
                fma2(acc[2], xx, dup2(p2[j]));
                fma2(acc[3], xx, dup2(p3[j]));
            }
        }

        // ---- finalize ----
        #pragma unroll
        for (int i = 0; i < 4; ++i) {
            float2 v = unpack2(acc[i]);
            float is = sinv[ib0 + i];
            float2 o = make_float2(v.x * is, v.y * is);
            *reinterpret_cast<float2*>(out + (b*L_ + i0 + ib0 + i)*D_ + dp*2) = o;
        }
    }
}

// ---------------------------------------------------------------------------
extern "C" void kernel_launch(void* const* d_in, const int* in_sizes, int n_in,
                              void* d_out, int out_size)
{
    const float* X  = (const float*)d_in[0];
    const float* Wt = (const float*)d_in[1];
    const float* Wx = (const float*)d_in[2];
    const float* bh = (const float*)d_in[3];
    const float* Wa = (const float*)d_in[4];
    // d_in[5] = ba : constant shift inside softmax -> mathematically a no-op

    proj_kernel<<<2*(B_*L_/16), 128>>>(X, Wt, Wx, bh);
    attn_kernel<<<B_*(NTROW/2), 256>>>(X, Wa, (float*)d_out);
}